// round 2
// baseline (speedup 1.0000x reference)
#include <cuda_runtime.h>
#include <math_constants.h>

#define BATCH 512
#define IN_DIM 1024
#define OUT_DIM 1024
#define KC 32
#define SMEM_LD 68   // row stride in floats: 16B-aligned (68*4=272), reduces bank conflicts

__global__ __launch_bounds__(256, 1)
void tropical_linear_kernel(const float* __restrict__ x,
                            const float* __restrict__ W,
                            float* __restrict__ y) {
    __shared__ float xs[KC][SMEM_LD];   // xs[k][b_local]
    __shared__ float ws[KC][SMEM_LD];   // ws[k][o_local]

    const int t  = threadIdx.x;
    const int tx = t & 15;      // o-direction thread coord (0..15)
    const int ty = t >> 4;      // b-direction thread coord (0..15)
    const int o0 = blockIdx.x * 64;
    const int b0 = blockIdx.y * 64;

    // global-load mapping: each thread loads 8 elements of x-tile and 8 of w-tile per chunk
    const int lc = t & 31;      // k-column within chunk (0..31) -> coalesced 128B lines
    const int lr = t >> 5;      // row group (0..7), rows lr + 8*j

    float acc[4][4];
#pragma unroll
    for (int i = 0; i < 4; i++)
#pragma unroll
        for (int j = 0; j < 4; j++)
            acc[i][j] = -CUDART_INF_F;

    const float* xp = x + (b0 + lr) * IN_DIM + lc;
    const float* wp = W + (o0 + lr) * IN_DIM + lc;

    // prologue: prefetch chunk 0 into registers
    float xg[8], wg[8];
#pragma unroll
    for (int j = 0; j < 8; j++) {
        xg[j] = xp[j * 8 * IN_DIM];
        wg[j] = wp[j * 8 * IN_DIM];
    }

    for (int k0 = 0; k0 < IN_DIM; k0 += KC) {
        // stage registers -> shared (transposed: [k][row])
#pragma unroll
        for (int j = 0; j < 8; j++) {
            xs[lc][lr + 8 * j] = xg[j];
            ws[lc][lr + 8 * j] = wg[j];
        }
        __syncthreads();

        // prefetch next chunk (hidden behind compute below)
        if (k0 + KC < IN_DIM) {
            const float* xp2 = xp + (k0 + KC);
            const float* wp2 = wp + (k0 + KC);
#pragma unroll
            for (int j = 0; j < 8; j++) {
                xg[j] = xp2[j * 8 * IN_DIM];
                wg[j] = wp2[j * 8 * IN_DIM];
            }
        }

        // compute: 4x4 register tile, max-plus accumulate
#pragma unroll
        for (int kk = 0; kk < KC; kk++) {
            float4 xf = *(const float4*)&xs[kk][ty * 4];
            float4 wf = *(const float4*)&ws[kk][tx * 4];
            float xa[4] = {xf.x, xf.y, xf.z, xf.w};
            float wa[4] = {wf.x, wf.y, wf.z, wf.w};
#pragma unroll
            for (int i = 0; i < 4; i++)
#pragma unroll
                for (int j = 0; j < 4; j++)
                    acc[i][j] = fmaxf(acc[i][j], xa[i] + wa[j]);
        }
        __syncthreads();
    }

    // epilogue: vectorized stores
#pragma unroll
    for (int i = 0; i < 4; i++) {
        const int b = b0 + ty * 4 + i;
        float4 v = make_float4(acc[i][0], acc[i][1], acc[i][2], acc[i][3]);
        *(float4*)&y[b * OUT_DIM + o0 + tx * 4] = v;
    }
}

extern "C" void kernel_launch(void* const* d_in, const int* in_sizes, int n_in,
                              void* d_out, int out_size) {
    const float* x = (const float*)d_in[0];   // [512, 1024]
    const float* W = (const float*)d_in[1];   // [1024, 1024]
    float* y = (float*)d_out;                  // [512, 1024]

    dim3 grid(OUT_DIM / 64, BATCH / 64);  // (16, 8) = 128 CTAs
    dim3 block(256);
    tropical_linear_kernel<<<grid, block>>>(x, W, y);
}

// round 6
// speedup vs baseline: 1.0373x; 1.0373x over previous
#include <cuda_runtime.h>
#include <math_constants.h>

#define BATCH 512
#define IN_DIM 1024
#define OUT_DIM 1024
#define KC 32
#define SMEM_LD 68   // row stride in floats (16B aligned, conflict-avoiding)
#define NCHUNK (IN_DIM / KC)

__global__ __launch_bounds__(256, 1)
void tropical_linear_kernel(const float* __restrict__ x,
                            const float* __restrict__ W,
                            float* __restrict__ y,
                            const float one) {  // runtime 1.0f: forces FFMA (fma pipe), not FADD (alu pipe)
    __shared__ float xs[2][KC][SMEM_LD];   // xs[buf][k][b_local]
    __shared__ float ws[2][KC][SMEM_LD];   // ws[buf][k][o_local]

    const int t  = threadIdx.x;
    const int tx = t & 15;      // o-direction (0..15)
    const int ty = t >> 4;      // b-direction (0..15)
    const int o0 = blockIdx.x * 64;
    const int b0 = blockIdx.y * 64;

    const int lc = t & 31;      // k within chunk -> coalesced
    const int lr = t >> 5;      // row group (0..7)

    float acc[4][4];
#pragma unroll
    for (int i = 0; i < 4; i++)
#pragma unroll
        for (int j = 0; j < 4; j++)
            acc[i][j] = -CUDART_INF_F;

    const float* xp = x + (b0 + lr) * IN_DIM + lc;
    const float* wp = W + (o0 + lr) * IN_DIM + lc;

    // prologue: chunk 0 -> regs -> smem buf 0
    float xg[8], wg[8];
#pragma unroll
    for (int j = 0; j < 8; j++) {
        xg[j] = xp[j * 8 * IN_DIM];
        wg[j] = wp[j * 8 * IN_DIM];
    }
#pragma unroll
    for (int j = 0; j < 8; j++) {
        xs[0][lc][lr + 8 * j] = xg[j];
        ws[0][lc][lr + 8 * j] = wg[j];
    }
    __syncthreads();

    for (int c = 0; c < NCHUNK; c++) {
        const int p = c & 1;

        // prefetch next chunk into registers (overlaps with compute)
        if (c + 1 < NCHUNK) {
            const float* xp2 = xp + (c + 1) * KC;
            const float* wp2 = wp + (c + 1) * KC;
#pragma unroll
            for (int j = 0; j < 8; j++) {
                xg[j] = xp2[j * 8 * IN_DIM];
                wg[j] = wp2[j * 8 * IN_DIM];
            }
        }

        // compute from buffer p: FFMA (fma pipe) + FMNMX (alu pipe), balanced
#pragma unroll
        for (int kk = 0; kk < KC; kk++) {
            float4 xf = *(const float4*)&xs[p][kk][ty * 4];
            float4 wf = *(const float4*)&ws[p][kk][tx * 4];
            float xa[4] = {xf.x, xf.y, xf.z, xf.w};
            float wa[4] = {wf.x, wf.y, wf.z, wf.w};
#pragma unroll
            for (int i = 0; i < 4; i++)
#pragma unroll
                for (int j = 0; j < 4; j++) {
                    float s = __fmaf_rn(xa[i], one, wa[j]);  // FFMA -> fma pipe
                    acc[i][j] = fmaxf(acc[i][j], s);         // FMNMX -> alu pipe
                }
        }

        // stage next chunk into the other buffer (no read/write conflict)
        if (c + 1 < NCHUNK) {
#pragma unroll
            for (int j = 0; j < 8; j++) {
                xs[p ^ 1][lc][lr + 8 * j] = xg[j];
                ws[p ^ 1][lc][lr + 8 * j] = wg[j];
            }
        }
        __syncthreads();
    }

    // epilogue: vectorized stores
#pragma unroll
    for (int i = 0; i < 4; i++) {
        const int b = b0 + ty * 4 + i;
        float4 v = make_float4(acc[i][0], acc[i][1], acc[i][2], acc[i][3]);
        *(float4*)&y[b * OUT_DIM + o0 + tx * 4] = v;
    }
}

extern "C" void kernel_launch(void* const* d_in, const int* in_sizes, int n_in,
                              void* d_out, int out_size) {
    const float* x = (const float*)d_in[0];   // [512, 1024]
    const float* W = (const float*)d_in[1];   // [1024, 1024]
    float* y = (float*)d_out;                  // [512, 1024]

    dim3 grid(OUT_DIM / 64, BATCH / 64);  // 128 CTAs, 1 wave
    dim3 block(256);
    tropical_linear_kernel<<<grid, block>>>(x, W, y, 1.0f);
}